// round 10
// baseline (speedup 1.0000x reference)
#include <cuda_runtime.h>
#include <cuda_fp16.h>
#include <math.h>
#include <stdint.h>

#define DM     1024
#define HEADS  16
#define DKH    64
#define BATCH  2
#define SEQ    2048
#define MROWS  (BATCH*SEQ)   // 4096

// Scratch (device globals; allocation-free per harness rules)
__device__ __half g_q[HEADS*BATCH*SEQ*DKH];    // head-layout projections
__device__ __half g_k[HEADS*BATCH*SEQ*DKH];
__device__ __half g_v[HEADS*BATCH*SEQ*DKH];
__device__ __half g_ctx[(size_t)MROWS*DM];     // attention output (concat)
__device__ __half g_xq[(size_t)MROWS*DM];      // fp16 copies of inputs
__device__ __half g_xk[(size_t)MROWS*DM];
__device__ __half g_xv[(size_t)MROWS*DM];
__device__ __half g_wq[(size_t)DM*DM];         // fp16 weights
__device__ __half g_wo[(size_t)DM*DM];

// ---- helpers --------------------------------------------------------------
__device__ __forceinline__ unsigned pack_h2(float a, float b) {
    __half2 h = __floats2half2_rn(a, b);
    return *reinterpret_cast<unsigned*>(&h);
}
__device__ __forceinline__ uint2 cvt_f4h(float4 v) {
    uint2 r; r.x = pack_h2(v.x, v.y); r.y = pack_h2(v.z, v.w); return r;
}
__device__ __forceinline__ void mma_f16(float d[4], const unsigned a[4],
                                        unsigned b0, unsigned b1) {
    asm("mma.sync.aligned.m16n8k16.row.col.f32.f16.f16.f32 "
        "{%0,%1,%2,%3}, {%4,%5,%6,%7}, {%8,%9}, {%0,%1,%2,%3};"
        : "+f"(d[0]), "+f"(d[1]), "+f"(d[2]), "+f"(d[3])
        : "r"(a[0]), "r"(a[1]), "r"(a[2]), "r"(a[3]), "r"(b0), "r"(b1));
}
__device__ __forceinline__ void ldsm_x4(unsigned r[4], unsigned saddr) {
    asm volatile("ldmatrix.sync.aligned.m8n8.x4.shared.b16 {%0,%1,%2,%3}, [%4];"
                 : "=r"(r[0]), "=r"(r[1]), "=r"(r[2]), "=r"(r[3])
                 : "r"(saddr));
}
__device__ __forceinline__ void ldsm_x4t(unsigned r[4], unsigned saddr) {
    asm volatile("ldmatrix.sync.aligned.m8n8.x4.trans.shared.b16 {%0,%1,%2,%3}, [%4];"
                 : "=r"(r[0]), "=r"(r[1]), "=r"(r[2]), "=r"(r[3])
                 : "r"(saddr));
}
__device__ __forceinline__ void cp16(unsigned dst, const void* src) {
    asm volatile("cp.async.ca.shared.global [%0], [%1], 16;"
                 :: "r"(dst), "l"(src));
}
__device__ __forceinline__ void cp_commit() {
    asm volatile("cp.async.commit_group;" ::: "memory");
}
template<int N>
__device__ __forceinline__ void cp_wait() {
    asm volatile("cp.async.wait_group %0;" :: "n"(N) : "memory");
}

// ---------------------------------------------------------------------------
// f32 -> f16 conversion: z selects {query,key,value,Wq,Wo}
// ---------------------------------------------------------------------------
__global__ void cvt_kernel(const float* __restrict__ q,
                           const float* __restrict__ k,
                           const float* __restrict__ v,
                           const float* __restrict__ wq,
                           const float* __restrict__ wo)
{
    const int z = blockIdx.z;
    const float* src; __half* dst; int nf4;
    if      (z == 0) { src = q;  dst = g_xq; nf4 = MROWS * DM / 4; }
    else if (z == 1) { src = k;  dst = g_xk; nf4 = MROWS * DM / 4; }
    else if (z == 2) { src = v;  dst = g_xv; nf4 = MROWS * DM / 4; }
    else if (z == 3) { src = wq; dst = g_wq; nf4 = DM * DM / 4; }
    else             { src = wo; dst = g_wo; nf4 = DM * DM / 4; }
    for (int i = blockIdx.x * blockDim.x + threadIdx.x; i < nf4;
         i += gridDim.x * blockDim.x) {
        float4 v4 = ((const float4*)src)[i];
        ((uint2*)dst)[i] = cvt_f4h(v4);
    }
}

// ---------------------------------------------------------------------------
// Fused q/k/v projection GEMM (z-fused): for one CTA tile [128m x 128n],
// stage the Wq k-tile ONCE per k-stage and apply it to the q, k, v A-tiles
// with three accumulator sets. B traffic and B-fragment LDSM drop 3x;
// 96 back-to-back mma per warp per stage hide latency even at 1 CTA/SM.
// 3-stage cp.async pipeline.
// ---------------------------------------------------------------------------
#define GA_STR 40
#define GB_STR 136
#define GA_HALFS (128 * GA_STR)            // 5120 per z
#define GB_HALFS (32 * GB_STR)             // 4352
#define Q_STAGE  (3 * GA_HALFS + GB_HALFS) // 19712 halfs
#define QKV_SMEM (3 * Q_STAGE * 2)         // 118272 bytes

__device__ __forceinline__ void qkv_stage(const __half* __restrict__ A0,
                                          const __half* __restrict__ A1,
                                          const __half* __restrict__ A2,
                                          const __half* __restrict__ W,
                                          unsigned smBase, int buf, int kt,
                                          int tid)
{
    const unsigned base = smBase + (unsigned)buf * (Q_STAGE * 2);
    const __half* As[3] = {A0, A1, A2};
#pragma unroll
    for (int z = 0; z < 3; z++) {
        const unsigned aB = base + (unsigned)z * (GA_HALFS * 2);
#pragma unroll
        for (int l = 0; l < 2; l++) {
            int c = tid + l * 256;
            int row = c >> 2, c16 = c & 3;
            cp16(aB + (row * GA_STR + c16 * 8) * 2,
                 As[z] + (size_t)row * DM + kt + c16 * 8);
        }
    }
    const unsigned bB = base + 3 * (GA_HALFS * 2);
#pragma unroll
    for (int l = 0; l < 2; l++) {
        int c = tid + l * 256;
        int row = c >> 4, c16 = c & 15;
        cp16(bB + (row * GB_STR + c16 * 8) * 2,
             W + (size_t)(kt + row) * DM + c16 * 8);
    }
}

__global__ __launch_bounds__(256, 1)
void gemm_qkv(const float* __restrict__ bias)
{
    extern __shared__ __half smh[];
    const unsigned smBase = (unsigned)__cvta_generic_to_shared(smh);

    const int tid  = threadIdx.x;
    const int warp = tid >> 5, lane = tid & 31;
    const int wm = warp >> 2, wn = warp & 3;
    const int grp = lane >> 2, qi = lane & 3;

    const int gm0 = blockIdx.y * 128;
    const int gn0 = blockIdx.x * 128;

    const __half* __restrict__ A0 = g_xq + (size_t)gm0 * DM;
    const __half* __restrict__ A1 = g_xk + (size_t)gm0 * DM;
    const __half* __restrict__ A2 = g_xv + (size_t)gm0 * DM;
    const __half* __restrict__ W  = g_wq + gn0;

    const unsigned aOff =
        (((wm * 64 + (lane & 7) + ((lane >> 3) & 1) * 8) * GA_STR)
         + (lane >> 4) * 8) * 2;
    const unsigned bOff = 3 * (GA_HALFS * 2) +
        ((((lane >> 3) * 8 + (lane & 7)) * GB_STR) + wn * 32) * 2;

    float d[3][4][4][4];
#pragma unroll
    for (int z = 0; z < 3; z++)
#pragma unroll
        for (int mi = 0; mi < 4; mi++)
#pragma unroll
            for (int ni = 0; ni < 4; ni++)
#pragma unroll
                for (int r = 0; r < 4; r++) d[z][mi][ni][r] = 0.f;

    qkv_stage(A0, A1, A2, W, smBase, 0, 0, tid);  cp_commit();
    qkv_stage(A0, A1, A2, W, smBase, 1, 32, tid); cp_commit();
    cp_wait<1>();
    __syncthreads();

    for (int it = 0; it < 32; it++) {
        const int buf = it % 3;
        if (it < 30)
            qkv_stage(A0, A1, A2, W, smBase, (it + 2) % 3, (it + 2) * 32, tid);
        cp_commit();

        const unsigned sB = smBase + (unsigned)buf * (Q_STAGE * 2);
        unsigned bf[4][4];
#pragma unroll
        for (int ni = 0; ni < 4; ni++)
            ldsm_x4t(bf[ni], sB + bOff + ni * 16);

#pragma unroll
        for (int z = 0; z < 3; z++) {
            const unsigned aZ = sB + (unsigned)z * (GA_HALFS * 2) + aOff;
#pragma unroll
            for (int kp = 0; kp < 2; kp++) {
                unsigned af[4][4];
#pragma unroll
                for (int mi = 0; mi < 4; mi++)
                    ldsm_x4(af[mi], aZ + mi * 16 * (GA_STR * 2) + kp * 32);
#pragma unroll
                for (int mi = 0; mi < 4; mi++)
#pragma unroll
                    for (int ni = 0; ni < 4; ni++)
                        mma_f16(d[z][mi][ni], af[mi],
                                bf[ni][kp * 2], bf[ni][kp * 2 + 1]);
            }
        }

        cp_wait<1>();
        __syncthreads();
    }

    // ---- epilogue: scatter all three projections to head layout (__half)
    const float qsc = rsqrtf((float)SEQ);
#pragma unroll
    for (int z = 0; z < 3; z++) {
        __half* out = (z == 0) ? g_q : (z == 1) ? g_k : g_v;
        const float sc = (z == 0) ? qsc : 1.0f;
#pragma unroll
        for (int ni = 0; ni < 4; ni++) {
            const int gcol = gn0 + wn * 32 + ni * 8 + qi * 2;
            const float b0 = bias[gcol], b1 = bias[gcol + 1];
            const int h = gcol >> 6, dd = gcol & 63;
#pragma unroll
            for (int mi = 0; mi < 4; mi++) {
                const int gr = gm0 + wm * 64 + mi * 16 + grp;
#pragma unroll
                for (int hh = 0; hh < 2; hh++) {
                    const int gm = gr + hh * 8;
                    const float v0 = (d[z][mi][ni][hh * 2 + 0] + b0) * sc;
                    const float v1 = (d[z][mi][ni][hh * 2 + 1] + b1) * sc;
                    const int b = gm >> 11, s = gm & (SEQ - 1);
                    *(unsigned*)&out[(((size_t)h * BATCH + b) * SEQ + s) * DKH + dd]
                        = pack_h2(v0, v1);
                }
            }
        }
    }
}

// ---------------------------------------------------------------------------
// Output projection GEMM (unchanged from R9): C = g_ctx @ g_wo + bo -> f32
// ---------------------------------------------------------------------------
#define G_STAGE  (GA_HALFS + GB_HALFS)     // 9472 halfs
#define GEMM_SMEM (3 * G_STAGE * 2)        // 56832 bytes

__device__ __forceinline__ void gemm_stage(const __half* __restrict__ A,
                                           const __half* __restrict__ W,
                                           unsigned smBase, int buf, int kt,
                                           int tid)
{
    const unsigned aB = smBase + (unsigned)buf * (G_STAGE * 2);
    const unsigned bB = aB + GA_HALFS * 2;
#pragma unroll
    for (int l = 0; l < 2; l++) {
        int c = tid + l * 256;
        int row = c >> 2, c16 = c & 3;
        cp16(aB + (row * GA_STR + c16 * 8) * 2,
             A + (size_t)row * DM + kt + c16 * 8);
    }
#pragma unroll
    for (int l = 0; l < 2; l++) {
        int c = tid + l * 256;
        int row = c >> 4, c16 = c & 15;
        cp16(bB + (row * GB_STR + c16 * 8) * 2,
             W + (size_t)(kt + row) * DM + c16 * 8);
    }
}

__global__ __launch_bounds__(256, 2)
void gemm_out(const float* __restrict__ bias, float* __restrict__ Cout)
{
    extern __shared__ __half smh[];
    const unsigned smBase = (unsigned)__cvta_generic_to_shared(smh);

    const int tid  = threadIdx.x;
    const int warp = tid >> 5, lane = tid & 31;
    const int wm = warp >> 2, wn = warp & 3;
    const int grp = lane >> 2, qi = lane & 3;

    const int gm0 = blockIdx.y * 128;
    const int gn0 = blockIdx.x * 128;

    const __half* __restrict__ A = g_ctx + (size_t)gm0 * DM;
    const __half* __restrict__ W = g_wo + gn0;

    const unsigned aOff =
        (((wm * 64 + (lane & 7) + ((lane >> 3) & 1) * 8) * GA_STR)
         + (lane >> 4) * 8) * 2;
    const unsigned bOff = GA_HALFS * 2 +
        ((((lane >> 3) * 8 + (lane & 7)) * GB_STR) + wn * 32) * 2;

    float d[4][4][4];
#pragma unroll
    for (int mi = 0; mi < 4; mi++)
#pragma unroll
        for (int ni = 0; ni < 4; ni++)
#pragma unroll
            for (int r = 0; r < 4; r++) d[mi][ni][r] = 0.f;

    gemm_stage(A, W, smBase, 0, 0, tid);  cp_commit();
    gemm_stage(A, W, smBase, 1, 32, tid); cp_commit();
    cp_wait<1>();
    __syncthreads();

    for (int it = 0; it < 32; it++) {
        const int buf = it % 3;
        if (it < 30)
            gemm_stage(A, W, smBase, (it + 2) % 3, (it + 2) * 32, tid);
        cp_commit();

        const unsigned sB = smBase + (unsigned)buf * (G_STAGE * 2);
        unsigned bf[4][4];
#pragma unroll
        for (int ni = 0; ni < 4; ni++)
            ldsm_x4t(bf[ni], sB + bOff + ni * 16);
#pragma unroll
        for (int kp = 0; kp < 2; kp++) {
            unsigned af[4][4];
#pragma unroll
            for (int mi = 0; mi < 4; mi++)
                ldsm_x4(af[mi], sB + aOff + mi * 16 * (GA_STR * 2) + kp * 32);
#pragma unroll
            for (int mi = 0; mi < 4; mi++)
#pragma unroll
                for (int ni = 0; ni < 4; ni++)
                    mma_f16(d[mi][ni], af[mi], bf[ni][kp * 2], bf[ni][kp * 2 + 1]);
        }

        cp_wait<1>();
        __syncthreads();
    }

#pragma unroll
    for (int ni = 0; ni < 4; ni++) {
        const int gcol = gn0 + wn * 32 + ni * 8 + qi * 2;
        const float b0 = bias[gcol], b1 = bias[gcol + 1];
#pragma unroll
        for (int mi = 0; mi < 4; mi++) {
            const int gr = gm0 + wm * 64 + mi * 16 + grp;
#pragma unroll
            for (int hh = 0; hh < 2; hh++) {
                const int gm = gr + hh * 8;
                *(float2*)&Cout[(size_t)gm * DM + gcol] =
                    make_float2(d[mi][ni][hh * 2 + 0] + b0,
                                d[mi][ni][hh * 2 + 1] + b1);
            }
        }
    }
}

// ---------------------------------------------------------------------------
// fp16 flash attention per (h,b) (unchanged from R9): BQ=256, 8 warps x 32
// q-rows; Q in registers; K/V via 3-stage cp.async; lane-local P packing.
// ---------------------------------------------------------------------------
#define KV_STR 72
#define KV_HALFS (64 * KV_STR)              // 4608 halfs (one K or V tile)
#define AT_STAGE (2 * KV_HALFS)             // 9216 halfs per stage
#define ATT_SMEM_BYTES (3 * AT_STAGE * 2)   // 55296 bytes

__device__ __forceinline__ void attn_stage(const __half* __restrict__ K,
                                           const __half* __restrict__ V,
                                           unsigned smBase, int buf,
                                           size_t kb, int tid)
{
    const unsigned base = smBase + (unsigned)buf * (AT_STAGE * 2);
#pragma unroll
    for (int l = 0; l < 2; l++) {
        int c = tid + l * 256;
        int row = c >> 3, c16 = c & 7;
        cp16(base + (row * KV_STR + c16 * 8) * 2,
             K + (kb + row) * DKH + c16 * 8);
    }
#pragma unroll
    for (int l = 0; l < 2; l++) {
        int c = tid + l * 256;
        int row = c >> 3, c16 = c & 7;
        cp16(base + KV_HALFS * 2 + (row * KV_STR + c16 * 8) * 2,
             V + (kb + row) * DKH + c16 * 8);
    }
}

__global__ __launch_bounds__(256)
void attn_kernel()
{
    extern __shared__ __half smh[];
    const unsigned smBase = (unsigned)__cvta_generic_to_shared(smh);

    const int tid  = threadIdx.x;
    const int warp = tid >> 5, lane = tid & 31;
    const int grp  = lane >> 2, qi = lane & 3;
    const int hb   = blockIdx.y;
    const int q0   = blockIdx.x * 256;

    const __half* __restrict__ Q = g_q + (size_t)hb * SEQ * DKH;
    const __half* __restrict__ K = g_k + (size_t)hb * SEQ * DKH;
    const __half* __restrict__ V = g_v + (size_t)hb * SEQ * DKH;

    const int row0 = warp * 32;
    const int rowL = tid >> 3, c8 = tid & 7;

    // ---- stage Q into (aliased) smem, ldmatrix to regs, then release smem
#pragma unroll
    for (int l = 0; l < 8; l++) {
        const int r = rowL + l * 32;
        uint4 v = *(const uint4*)&Q[(size_t)(q0 + r) * DKH + c8 * 8];
        *(uint4*)&smh[r * KV_STR + c8 * 8] = v;
    }
    __syncthreads();

    unsigned qf[2][4][4];
    {
        const unsigned qLane = smBase +
            (((row0 + (lane & 7) + ((lane >> 3) & 1) * 8) * KV_STR)
             + (lane >> 4) * 8) * 2;
#pragma unroll
        for (int m = 0; m < 2; m++)
#pragma unroll
            for (int kp = 0; kp < 4; kp++)
                ldsm_x4(qf[m][kp], qLane + m * 16 * (KV_STR * 2) + kp * 32);
    }
    __syncthreads();

    const unsigned kOff = (((lane & 7) * KV_STR) + (lane >> 3) * 8) * 2;
    const unsigned vOff = KV_HALFS * 2 +
        (((lane >> 3) * 8 + (lane & 7)) * KV_STR) * 2;

    float o[2][8][4];
    float rs[2][2];
#pragma unroll
    for (int m = 0; m < 2; m++) {
        rs[m][0] = 0.f; rs[m][1] = 0.f;
#pragma unroll
        for (int ni = 0; ni < 8; ni++)
#pragma unroll
            for (int r = 0; r < 4; r++) o[m][ni][r] = 0.f;
    }

    attn_stage(K, V, smBase, 0, 0, tid);  cp_commit();
    attn_stage(K, V, smBase, 1, 64, tid); cp_commit();
    cp_wait<1>();
    __syncthreads();

    for (int it = 0; it < 32; it++) {
        const int buf = it % 3;
        if (it < 30)
            attn_stage(K, V, smBase, (it + 2) % 3, (size_t)(it + 2) * 64, tid);
        cp_commit();

        const unsigned sB = smBase + (unsigned)buf * (AT_STAGE * 2);

        float s[2][8][4];
#pragma unroll
        for (int m = 0; m < 2; m++)
#pragma unroll
            for (int ni = 0; ni < 8; ni++)
#pragma unroll
                for (int r = 0; r < 4; r++) s[m][ni][r] = 0.f;

#pragma unroll
        for (int kq = 0; kq < 2; kq++) {
#pragma unroll
            for (int ni = 0; ni < 8; ni++) {
                unsigned kf[4];
                ldsm_x4(kf, sB + kOff + (ni * 8 * KV_STR) * 2 + kq * 64);
#pragma unroll
                for (int m = 0; m < 2; m++) {
                    mma_f16(s[m][ni], qf[m][2 * kq],     kf[0], kf[1]);
                    mma_f16(s[m][ni], qf[m][2 * kq + 1], kf[2], kf[3]);
                }
            }
        }

        unsigned ps[2][4][4];
#pragma unroll
        for (int m = 0; m < 2; m++)
#pragma unroll
            for (int tp = 0; tp < 4; tp++) {
                const float* sa = s[m][2 * tp];
                const float* sb = s[m][2 * tp + 1];
                float e0 = __expf(sa[0]), e1 = __expf(sa[1]);
                float e2 = __expf(sa[2]), e3 = __expf(sa[3]);
                float f0 = __expf(sb[0]), f1 = __expf(sb[1]);
                float f2 = __expf(sb[2]), f3 = __expf(sb[3]);
                rs[m][0] += (e0 + e1) + (f0 + f1);
                rs[m][1] += (e2 + e3) + (f2 + f3);
                ps[m][tp][0] = pack_h2(e0, e1);
                ps[m][tp][1] = pack_h2(e2, e3);
                ps[m][tp][2] = pack_h2(f0, f1);
                ps[m][tp][3] = pack_h2(f2, f3);
            }

#pragma unroll
        for (int tq = 0; tq < 2; tq++) {
#pragma unroll
            for (int ni = 0; ni < 8; ni++) {
                unsigned vf[4];
                ldsm_x4t(vf, sB + vOff + (tq * 32 * KV_STR) * 2 + ni * 16);
#pragma unroll
                for (int m = 0; m < 2; m++) {
                    mma_f16(o[m][ni], ps[m][2 * tq],     vf[0], vf[1]);
                    mma_f16(o[m][ni], ps[m][2 * tq + 1], vf[2], vf[3]);
                }
            }
        }

        cp_wait<1>();
        __syncthreads();
    }

#pragma unroll
    for (int m = 0; m < 2; m++)
#pragma unroll
        for (int j = 0; j < 2; j++) {
            float r = rs[m][j];
            r += __shfl_xor_sync(0xffffffffu, r, 1);
            r += __shfl_xor_sync(0xffffffffu, r, 2);
            rs[m][j] = 1.f / r;
        }

    const int h = hb >> 1, b = hb & 1;
#pragma unroll
    for (int m = 0; m < 2; m++) {
        const int sr0 = q0 + row0 + m * 16 + grp;
#pragma unroll
        for (int ni = 0; ni < 8; ni++) {
            const int col = h * DKH + ni * 8 + qi * 2;
            *(unsigned*)&g_ctx[((size_t)(b * SEQ + sr0)) * DM + col] =
                pack_h2(o[m][ni][0] * rs[m][0], o[m][ni][1] * rs[m][0]);
            *(unsigned*)&g_ctx[((size_t)(b * SEQ + sr0 + 8)) * DM + col] =
                pack_h2(o[m][ni][2] * rs[m][1], o[m][ni][3] * rs[m][1]);
        }
    }
}

// ---------------------------------------------------------------------------
extern "C" void kernel_launch(void* const* d_in, const int* in_sizes, int n_in,
                              void* d_out, int out_size)
{
    (void)in_sizes; (void)n_in; (void)out_size;
    const float* query = (const float*)d_in[0];
    const float* key   = (const float*)d_in[1];
    const float* value = (const float*)d_in[2];
    const float* Wq    = (const float*)d_in[3];
    const float* bq    = (const float*)d_in[4];
    const float* Wo    = (const float*)d_in[5];
    const float* bo    = (const float*)d_in[6];
    float* out = (float*)d_out;

    cudaFuncSetAttribute(gemm_qkv,
                         cudaFuncAttributeMaxDynamicSharedMemorySize, QKV_SMEM);
    cudaFuncSetAttribute(gemm_out,
                         cudaFuncAttributeMaxDynamicSharedMemorySize, GEMM_SMEM);
    cudaFuncSetAttribute(attn_kernel,
                         cudaFuncAttributeMaxDynamicSharedMemorySize,
                         ATT_SMEM_BYTES);

    dim3 blk(256);
    cvt_kernel<<<dim3(1024, 1, 5), blk>>>(query, key, value, Wq, Wo);
    gemm_qkv<<<dim3(DM / 128, MROWS / 128), blk, QKV_SMEM>>>(bq);
    attn_kernel<<<dim3(SEQ / 256, HEADS * BATCH), blk, ATT_SMEM_BYTES>>>();
    gemm_out<<<dim3(DM / 128, MROWS / 128), blk, GEMM_SMEM>>>(bo, out);
}